// round 5
// baseline (speedup 1.0000x reference)
#include <cuda_runtime.h>
#include <math.h>

// Scratch for per-point min squared distances (bits of nonnegative floats,
// order-preserving as unsigned). [0..N) = pred->gt, [N..2N) = gt->pred.
// Max N supported here: 65536 points per cloud (problem uses 16384).
#define MAX_PTS 65536
__device__ unsigned g_minbits[2 * MAX_PTS];

#define BLOCK 256
#define TX 8
#define XTILE (BLOCK * TX)   // 2048 x-points per block
#define YT 256               // y sub-tile resident in smem

__global__ void init_minbits_kernel(int total) {
    int i = blockIdx.x * blockDim.x + threadIdx.x;
    if (i < total) g_minbits[i] = 0x7F800000u;  // +inf
}

// One direction: for each x in X, min over all y in Y of ||x-y||^2.
// d2 = sx + sy - 2 x.y ; sx is constant per x, so the inner loop tracks
// acc = sy - 2 x.y only (3 FFMA + 1 FMNMX per pair), sx added at the end.
__global__ __launch_bounds__(BLOCK) void chamfer_pass_kernel(
    const float* __restrict__ X, const float* __restrict__ Y,
    int N, int ychunk, int outOff)
{
    __shared__ float4 sy[YT];

    const int xbase = blockIdx.x * XTILE;
    const int ybeg = blockIdx.y * ychunk;
    const int yend = min(ybeg + ychunk, N);

    float x0[TX], x1[TX], x2[TX], mn[TX];
#pragma unroll
    for (int t = 0; t < TX; t++) {
        int xi = xbase + t * BLOCK + threadIdx.x;
        if (xi < N) {
            x0[t] = X[3 * xi + 0];
            x1[t] = X[3 * xi + 1];
            x2[t] = X[3 * xi + 2];
        } else {
            x0[t] = x1[t] = x2[t] = 0.0f;
        }
        mn[t] = INFINITY;
    }

    for (int ybase = ybeg; ybase < yend; ybase += YT) {
        __syncthreads();
        // cooperative load + pre-transform of y tile: (-2y0,-2y1,-2y2, ||y||^2)
        for (int j = threadIdx.x; j < YT; j += BLOCK) {
            int yi = ybase + j;
            float4 v;
            if (yi < yend) {
                float a = Y[3 * yi + 0];
                float b = Y[3 * yi + 1];
                float c = Y[3 * yi + 2];
                v = make_float4(-2.0f * a, -2.0f * b, -2.0f * c,
                                fmaf(a, a, fmaf(b, b, c * c)));
            } else {
                // padding: huge sy, zero coords -> acc huge, never the min
                v = make_float4(0.0f, 0.0f, 0.0f, 3.0e38f);
            }
            sy[j] = v;
        }
        __syncthreads();

#pragma unroll 4
        for (int j = 0; j < YT; j++) {
            float4 v = sy[j];
#pragma unroll
            for (int t = 0; t < TX; t++) {
                float acc = fmaf(x0[t], v.x, v.w);
                acc = fmaf(x1[t], v.y, acc);
                acc = fmaf(x2[t], v.z, acc);
                mn[t] = fminf(mn[t], acc);
            }
        }
    }

#pragma unroll
    for (int t = 0; t < TX; t++) {
        int xi = xbase + t * BLOCK + threadIdx.x;
        if (xi < N) {
            float sx = fmaf(x0[t], x0[t], fmaf(x1[t], x1[t], x2[t] * x2[t]));
            float d2 = fmaxf(mn[t] + sx, 0.0f);
            atomicMin(&g_minbits[outOff + xi], __float_as_uint(d2));
        }
    }
}

// Final reduction: mean(sqrt(min d2)) over each direction, sum the two means.
__global__ void chamfer_reduce_kernel(float* __restrict__ out, int N) {
    __shared__ float warpsum[32];
    float s = 0.0f;
    for (int i = threadIdx.x; i < 2 * N; i += blockDim.x) {
        float d2 = fmaxf(__uint_as_float(g_minbits[i]), 0.0f);
        s += sqrtf(d2);
    }
    // warp reduce
    for (int off = 16; off > 0; off >>= 1)
        s += __shfl_down_sync(0xFFFFFFFFu, s, off);
    int wid = threadIdx.x >> 5;
    int lid = threadIdx.x & 31;
    if (lid == 0) warpsum[wid] = s;
    __syncthreads();
    int nwarps = blockDim.x >> 5;
    if (wid == 0) {
        float v = (lid < nwarps) ? warpsum[lid] : 0.0f;
        for (int off = 16; off > 0; off >>= 1)
            v += __shfl_down_sync(0xFFFFFFFFu, v, off);
        if (lid == 0) out[0] = v / (float)N;  // (sum0+sum1)/N = mean0+mean1
    }
}

extern "C" void kernel_launch(void* const* d_in, const int* in_sizes, int n_in,
                              void* d_out, int out_size) {
    const float* pred = (const float*)d_in[0];
    const float* gt   = (const float*)d_in[1];
    float* out = (float*)d_out;

    const int N = in_sizes[0] / 3;  // 16384 points per cloud

    // 1) init min buffers to +inf
    {
        int total = 2 * N;
        int blocks = (total + 511) / 512;
        init_minbits_kernel<<<blocks, 512>>>(total);
    }

    // 2) two direction passes
    const int ychunk = 512;
    dim3 grid((N + XTILE - 1) / XTILE, (N + ychunk - 1) / ychunk);
    chamfer_pass_kernel<<<grid, BLOCK>>>(pred, gt, N, ychunk, 0);
    chamfer_pass_kernel<<<grid, BLOCK>>>(gt, pred, N, ychunk, N);

    // 3) scalar reduction
    chamfer_reduce_kernel<<<1, 1024>>>(out, N);
}